// round 16
// baseline (speedup 1.0000x reference)
#include <cuda_runtime.h>

#define NA      102000
#define NFEAT   85
#define NC      80
#define KSEL    8192
#define CAP     16384
#define MAXDET  300
#define CONF    0.25f
#define IOUT    0.45f
#define MWORDS  256     // KSEL/32
#define NBLK    8       // KSEL/1024
#define NB      148     // persistent blocks (1 per SM, co-resident)
#define NT      1024
#define SMEM_BYTES 131072

// ---------------- device scratch (zero-init at load; invariants restored per call) ----
__device__ unsigned int       g_arrive;
__device__ unsigned int       g_status;         // scan progress: low16 = blocks done, bit31 = done
__device__ unsigned int       g_keys[NA];
__device__ unsigned int       g_hist1[65536];
__device__ unsigned int       g_T;
__device__ unsigned int       g_cnt;
__device__ unsigned int       g_nk;
__device__ unsigned int       g_kept[MAXDET];
__device__ unsigned long long g_surv[CAP];
__device__ int                g_rank[CAP];      // written before read each call
__device__ float4             g_top_box[KSEL];
__device__ float              g_top_area[KSEL];
__device__ float              g_top_score[KSEL];
__device__ float              g_top_cls[KSEL];
__device__ unsigned int       g_mask[KSEL * MWORDS];   // only demanded words written; sub-diagonal stays 0

// grid-wide barrier: arrival = atomic; wait = plain volatile load
__device__ __forceinline__ void gbar(unsigned e) {
    __syncthreads();
    if (threadIdx.x == 0) {
        __threadfence();
        atomicAdd(&g_arrive, 1u);
        while (*(volatile unsigned*)&g_arrive < e * NB) { }
        __threadfence();
    }
    __syncthreads();
}

// 256-wide suffix-sum select (tid<256 carry data); final inclusive suffix left in sA
__device__ __forceinline__ int suffix_sel_1024(unsigned* sA, unsigned* sB, int* sres,
                                               int tid, unsigned v, unsigned target) {
    if (tid < 256) sA[tid] = v;
    __syncthreads();
    unsigned* src = sA; unsigned* dst = sB;
    #pragma unroll
    for (int d = 1; d < 256; d <<= 1) {
        unsigned x = 0;
        if (tid < 256) { x = src[tid]; if (tid + d < 256) x += src[tid + d]; }
        if (tid < 256) dst[tid] = x;
        __syncthreads();
        unsigned* t2 = src; src = dst; dst = t2;
    }   // 8 swaps -> suffix back in sA
    if (tid == 0) *sres = -1;
    __syncthreads();
    if (tid < 256 && sA[tid] >= target) atomicMax(sres, tid);
    __syncthreads();
    return *sres;
}

extern "C" __global__ void __launch_bounds__(NT, 1)
yolo_all(const float* __restrict__ preds, float* __restrict__ out, int n) {
    extern __shared__ char dsm[];
    __shared__ unsigned s_sA[256], s_sB[256];
    __shared__ int s_res;
    __shared__ int kept[MAXDET];
    __shared__ unsigned blocksup[32];
    __shared__ unsigned s_T, s_st;
    __shared__ int s_kept, s_skip, s_prev;

    int tid = threadIdx.x;
    int blk = blockIdx.x;
    int g = blk * NT + tid;

    // ---- P0: zero per-call state ----
    if (g < 65536) g_hist1[g] = 0u;
    if (g < KSEL)  g_top_score[g] = 0.f;
    if (g == 0)    { g_cnt = 0u; g_nk = 0u; g_T = 0u; g_status = 0u; }
    gbar(1);

    // ---- P1: scores; fmax split 4 ways per anchor (max exact; *obj monotone) ----
    {
        float* sf   = (float*)dsm;                 // 87040 B
        float4* sf4 = (float4*)dsm;
        float* qmax = (float*)(dsm + 87040);       // 4 KB
        int ntile = (n + 255) / 256;
        for (int tile = blk; tile < ntile; tile += NB) {
            int base = tile * 256;
            int cnt_t = n - base; if (cnt_t > 256) cnt_t = 256;
            int nel = cnt_t * NFEAT;
            int nel4 = nel >> 2;
            const float*  src  = preds + (size_t)base * NFEAT;
            const float4* src4 = (const float4*)src;      // base*85*4 % 16 == 0
            __syncthreads();
            for (int i = tid; i < nel4; i += NT) sf4[i] = src4[i];
            for (int i = (nel4 << 2) + tid; i < nel; i += NT) sf[i] = src[i];
            __syncthreads();
            {
                int anchor = tid & 255, q = tid >> 8;     // 4 threads per anchor
                const float* p = &sf[anchor * NFEAT];     // stride 85: conflict-free
                int c0 = 5 + q * 20;
                float m = p[c0];
                #pragma unroll
                for (int k = 1; k < 20; k++) m = fmaxf(m, p[c0 + k]);
                qmax[(q << 8) + anchor] = m;
            }
            __syncthreads();
            if (tid < cnt_t) {
                float m = fmaxf(fmaxf(qmax[tid], qmax[256 + tid]),
                                fmaxf(qmax[512 + tid], qmax[768 + tid]));
                float obj = sf[tid * NFEAT + 4];
                float score = (obj > CONF) ? __fmul_rn(m, obj) : 0.0f;
                unsigned key = __float_as_uint(score);
                g_keys[base + tid] = key;
                if (key) atomicAdd(&g_hist1[key >> 16], 1u);
            }
        }
    }
    gbar(2);

    // ---- P2: coarse threshold -> g_T; block 0 produces (wide hist sum), others poll ----
    if (blk == 0) {
        unsigned* s4 = (unsigned*)dsm;             // 4 KB scratch
        unsigned s = 0;
        {
            const unsigned* h = g_hist1 + tid * 64;
            #pragma unroll 8
            for (int k2 = 0; k2 < 64; k2++) s += h[k2];   // independent loads: MLP
        }
        s4[tid] = s;
        __syncthreads();
        unsigned v = 0;
        if (tid < 256) {
            int b4 = tid << 2;
            v = s4[b4] + s4[b4 + 1] + s4[b4 + 2] + s4[b4 + 3];
        }
        __syncthreads();
        int C = suffix_sel_1024(s_sA, s_sB, &s_res, tid, v, KSEL);
        unsigned T;
        if (C < 0) {
            T = 1u;                               // fewer than KSEL positives: take all
        } else {
            unsigned A1 = (C < 255) ? s_sA[C + 1] : 0u;
            __syncthreads();
            unsigned e = (tid < 256) ? g_hist1[C * 256 + tid] : 0u;
            int b = suffix_sel_1024(s_sA, s_sB, &s_res, tid, e, (unsigned)KSEL - A1);
            T = ((unsigned)(C * 256 + b)) << 16;
            if (!T) T = 1u;                       // never admit score==0
        }
        if (tid == 0) { s_T = T; __threadfence(); g_T = T; }
        __syncthreads();
    } else {
        if (tid == 0) {
            unsigned T;
            do { T = *(volatile unsigned*)&g_T; } while (!T);
            s_T = T;
        }
        __syncthreads();
    }

    // ---- P3: compact survivors (coarse superset of top-K), warp-aggregated ----
    {
        unsigned T = s_T;
        bool pred = false; unsigned key = 0;
        if (g < n) { key = g_keys[g]; pred = (key >= T); }
        unsigned m = __ballot_sync(0xffffffffu, pred);
        if (m) {
            int lane = tid & 31;
            int leader = __ffs(m) - 1;
            unsigned base2 = 0;
            if (lane == leader) base2 = atomicAdd(&g_cnt, (unsigned)__popc(m));
            base2 = __shfl_sync(0xffffffffu, base2, leader);
            if (pred) {
                unsigned pos = base2 + (unsigned)__popc(m & ((1u << lane) - 1u));
                if (pos < CAP)
                    g_surv[pos] = ((unsigned long long)key << 32) | (unsigned)(~g);
            }
        }
    }
    gbar(3);

    // ---- P4: exact global rank; all keys smem-resident, 16-lane groups, direct store ----
    {
        unsigned long long* skeys = (unsigned long long*)dsm;   // <=128 KB
        unsigned cntu = g_cnt; if (cntu > CAP) cntu = CAP;
        int cnt = (int)cntu;
        __syncthreads();
        for (int j = tid; j < cnt; j += NT) skeys[j] = g_surv[j];
        __syncthreads();
        int lane16 = tid & 15;
        #pragma unroll
        for (int itr = 0; itr < 2; itr++) {
            int gbase = blk * 64 + itr * (NB * 64);
            if (gbase >= cnt) break;                  // block-uniform
            int gid = gbase + (tid >> 4);
            bool act = gid < cnt;
            unsigned long long key = act ? skeys[gid] : 0xFFFFFFFFFFFFFFFFULL;
            int r = 0;
            #pragma unroll 4
            for (int j = lane16; j < cnt; j += 16)
                r += (skeys[j] > key) ? 1 : 0;
            r += __shfl_xor_sync(0xffffffffu, r, 8, 16);
            r += __shfl_xor_sync(0xffffffffu, r, 4, 16);
            r += __shfl_xor_sync(0xffffffffu, r, 2, 16);
            r += __shfl_xor_sync(0xffffffffu, r, 1, 16);
            if (act && lane16 == 0) g_rank[gid] = r;
        }
    }
    gbar(4);

    // ---- P5: scatter to rank (<KSEL) + gather box/area/score + exact argmax ----
    {
        unsigned cntu = g_cnt; if (cntu > CAP) cntu = CAP;
        int cnt = (int)cntu;
        for (int c = blk; c * 256 < cnt; c += NB) {
            int i = c * 256 + tid;
            if (tid < 256 && i < cnt) {
                int r = g_rank[i];
                if (r < KSEL) {
                    unsigned long long key = g_surv[i];
                    unsigned idx = ~(unsigned)(key & 0xFFFFFFFFu);
                    float score = __uint_as_float((unsigned)(key >> 32));
                    const float* p = preds + (size_t)idx * NFEAT;
                    float x = p[0], y = p[1], w = p[2], h = p[3];
                    float hh = __fmul_rn(h, 0.5f), hw = __fmul_rn(w, 0.5f);
                    float4 box;
                    box.x = __fsub_rn(y, hh);
                    box.y = __fsub_rn(x, hw);
                    box.z = __fadd_rn(y, hh);
                    box.w = __fadd_rn(x, hw);
                    float area = __fmul_rn(__fsub_rn(box.z, box.x), __fsub_rn(box.w, box.y));
                    float obj = p[4];
                    float best = -1.0f; int bi = 0;
                    #pragma unroll 4
                    for (int cc = 0; cc < NC; cc++) {
                        float v = __fmul_rn(p[5 + cc], obj);   // exact reference argmax order
                        if (v > best) { best = v; bi = cc; }
                    }
                    g_top_box[r]   = box;
                    g_top_area[r]  = area;
                    g_top_score[r] = score;
                    g_top_cls[r]   = (float)bi;
                }
            }
        }
    }
    gbar(5);

    // ---- P6/P7 fused: lazy mask + word-ordered local-chain scan ----
    {
        const float BHI = 0.4500045f;   // above -> surely iou>0.45 (margin >> fp32 err)
        const float BLO = 0.4499955f;   // below -> surely not
        unsigned* sm = (unsigned*)dsm;  // 128 KB diag buffer (block 0)
        int warp = tid >> 5, lane = tid & 31;
        const unsigned FULL = 0xffffffffu;
        if (blk == 0 && tid == 0) s_kept = 0;
        for (int b = 0; b < NBLK; b++) {
            // -- coop phase (all blocks): diag block b + kept-rows x block-b words --
            {
                unsigned nk = *(volatile unsigned*)&g_nk;
                int nkg = ((int)nk + 31) >> 5;
                int totalw = 1024 + nkg * 32;            // warp-units
                int gw = blk * 32 + warp;
                for (int u = gw; u < totalw; u += NB * 32) {
                    int row, jw; bool vrow = true;
                    if (u < 1024) {
                        int rg = u >> 5, wl = u & 31;
                        if (wl < rg) continue;           // sub-diagonal: never read, stays 0
                        row = (b << 10) + (rg << 5) + lane;
                        jw = (b << 5) + wl;
                    } else {
                        int v2 = u - 1024;
                        int ki = ((v2 >> 5) << 5) + lane;
                        vrow = (ki < (int)nk);
                        row = vrow ? (int)*(volatile unsigned*)&g_kept[ki] : 0;
                        jw = (b << 5) + (v2 & 31);
                    }
                    float4 bb = g_top_box[row];
                    float ai = g_top_area[row];
                    const float4* jb = &g_top_box[jw << 5];
                    const float*  ja = &g_top_area[jw << 5];
                    unsigned word = 0, band = 0;
                    #pragma unroll 8
                    for (int c2 = 0; c2 < 32; c2++) {
                        float4 bj = jb[c2];              // uniform addr -> broadcast
                        float aj = ja[c2];
                        float ty  = fmaxf(bb.x, bj.x);
                        float tx  = fmaxf(bb.y, bj.y);
                        float byv = fminf(bb.z, bj.z);
                        float bxv = fminf(bb.w, bj.w);
                        float ih = fmaxf(__fsub_rn(byv, ty), 0.f);
                        float iw = fmaxf(__fsub_rn(bxv, tx), 0.f);
                        float inter = __fmul_rn(ih, iw);
                        float den = __fadd_rn(__fsub_rn(__fadd_rn(ai, aj), inter), 1e-9f);
                        bool hi = inter > __fmul_rn(BHI, den);
                        bool bd = !hi && (inter > __fmul_rn(BLO, den));
                        word |= hi ? (1u << c2) : 0u;
                        band |= bd ? (1u << c2) : 0u;
                    }
                    if (jw == (row >> 5)) {              // diagonal word: only j > row
                        unsigned dm = 0xFFFFFFFEu << (row & 31);
                        word &= dm; band &= dm;
                    }
                    if (band) {   // essentially never: exact division for ambiguous pairs
                        while (band) {
                            int c2 = __ffs(band) - 1; band &= band - 1;
                            float4 bj = jb[c2];
                            float aj = ja[c2];
                            float ty  = fmaxf(bb.x, bj.x);
                            float tx  = fmaxf(bb.y, bj.y);
                            float byv = fminf(bb.z, bj.z);
                            float bxv = fminf(bb.w, bj.w);
                            float ih = fmaxf(__fsub_rn(byv, ty), 0.f);
                            float iw = fmaxf(__fsub_rn(bxv, tx), 0.f);
                            float inter = __fmul_rn(ih, iw);
                            float den = __fadd_rn(__fsub_rn(__fadd_rn(ai, aj), inter), 1e-9f);
                            if (__fdiv_rn(inter, den) > IOUT) word |= (1u << c2);
                        }
                    }
                    if (vrow) g_mask[(size_t)row * MWORDS + jw] = word;
                }
            }
            // -- arrival (all blocks); only block 0 waits --
            __syncthreads();
            if (tid == 0) { __threadfence(); atomicAdd(&g_arrive, 1u); }

            if (blk == 0) {
                if (tid == 0) {
                    unsigned target = (unsigned)(6 + b) * NB;
                    while (*(volatile unsigned*)&g_arrive < target) { }
                    __threadfence();
                }
                __syncthreads();
                // -- scan block b --
                if (s_kept < MAXDET) {
                    {
                        float s = g_top_score[(b << 10) + (warp << 5) + lane];
                        unsigned inval = __ballot_sync(FULL, !(s > 0.f));
                        unsigned v = 0;
                        int nk0 = s_kept;
                        for (int k = lane; k < nk0; k += 32)
                            v |= g_mask[(size_t)kept[k] * MWORDS + (b << 5) + warp];
                        v = __reduce_or_sync(FULL, v) | inval;
                        if (lane == 0) blocksup[warp] = v;
                    }
                    __syncthreads();
                    if (tid < 32) {
                        unsigned v = blocksup[lane];
                        unsigned full = __ballot_sync(FULL, v == 0xFFFFFFFFu);
                        if (lane == 0) s_skip = (full == 0xFFFFFFFFu) ? 1 : 0;
                    }
                    if (tid == 0) s_prev = s_kept;
                    __syncthreads();
                    if (!s_skip) {
                        for (int u = tid; u < 8192; u += 1024) {   // diag block -> smem
                            int i = u >> 3, w4 = u & 7;
                            ((uint4*)sm)[u] =
                                ((const uint4*)(g_mask + (size_t)((b << 10) + i) * MWORDS + (b << 5)))[w4];
                        }
                        __syncthreads();
                        if (tid < 32) {
                            unsigned sup_w = blocksup[lane];
                            int cnt = s_kept;
                            int base = b << 10;
                            for (int w = 0; w < 32 && cnt < MAXDET; w++) {
                                unsigned acc = 0;
                                if (lane == w) {
                                    // local accept chain: liveness + same-word row bits all in-lane
                                    unsigned Lv = ~sup_w;
                                    int room = MAXDET - cnt;
                                    while (Lv && room > 0) {
                                        int c = __ffs(Lv) - 1;
                                        acc |= 1u << c;
                                        room--;
                                        unsigned rw = sm[(((w << 5) + c) << 5) + w];
                                        Lv &= ~(rw | (1u << c));
                                    }
                                }
                                acc = __shfl_sync(FULL, acc, w);
                                if (acc) {
                                    int k = __popc(acc);
                                    if (lane < k) {
                                        int nth = __fns(acc, 0, lane + 1);
                                        kept[cnt + lane] = base + (w << 5) + nth;
                                    }
                                    unsigned a2 = acc;
                                    while (a2) {                  // independent LDS: MLP
                                        int c = __ffs(a2) - 1; a2 &= a2 - 1;
                                        sup_w |= sm[(((w << 5) + c) << 5) + lane];
                                    }
                                    if (lane == w) sup_w |= acc;
                                    cnt += k;
                                }
                            }
                            if (lane == 0) s_kept = cnt;
                        }
                        __syncthreads();
                    }
                    // publish new keeps, then status
                    for (int t = s_prev + tid; t < s_kept; t += NT)
                        g_kept[t] = (unsigned)kept[t];
                }
                __syncthreads();
                if (tid == 0) {
                    g_nk = (unsigned)s_kept;
                    unsigned done = (s_kept >= MAXDET || b == NBLK - 1) ? 0x80000000u : 0u;
                    __threadfence();
                    g_status = (unsigned)(b + 1) | done;
                    s_st = (unsigned)(b + 1) | done;
                }
                __syncthreads();
                if (s_st & 0x80000000u) break;
            } else {
                // non-zero blocks: poll status for this iteration
                if (tid == 0) {
                    unsigned st;
                    do { st = *(volatile unsigned*)&g_status; }
                    while ((st & 0xFFFFu) < (unsigned)(b + 1) && !(st & 0x80000000u));
                    __threadfence();
                    s_st = st;
                }
                __syncthreads();
                if (s_st & 0x80000000u) break;
            }
        }
    }

    // ---- output (block 0; others exit) ----
    if (blk != 0) return;
    {
        int m = s_kept;
        for (int t = tid; t < MAXDET; t += 1024) {
            float4 bx = make_float4(0.f, 0.f, 0.f, 0.f);
            float c = 0.f, s = 0.f;
            if (t < m) {
                int ki = kept[t];
                bx = g_top_box[ki];
                c = g_top_cls[ki];
                s = g_top_score[ki];
            }
            out[4 * t + 0] = bx.x; out[4 * t + 1] = bx.y;
            out[4 * t + 2] = bx.z; out[4 * t + 3] = bx.w;
            out[1200 + t] = c;
            out[1500 + t] = s;
        }
        __syncthreads();
        if (tid == 0) g_arrive = 0u;   // reset barrier for next (graph-replayed) call
    }
}

// ---------------- launch: ONE kernel node ----------------
extern "C" void kernel_launch(void* const* d_in, const int* in_sizes, int n_in,
                              void* d_out, int out_size) {
    const float* preds = (const float*)d_in[0];
    float* out = (float*)d_out;
    int n = in_sizes[0] / NFEAT;
    if (n > NA) n = NA;

    cudaFuncSetAttribute(yolo_all, cudaFuncAttributeMaxDynamicSharedMemorySize, SMEM_BYTES);
    yolo_all<<<NB, NT, SMEM_BYTES>>>(preds, out, n);
}